// round 11
// baseline (speedup 1.0000x reference)
#include <cuda_runtime.h>

#define B 16
#define G 5000
#define K 256
#define HID 64
#define STEPS 10
#define NCHUNK 148
#define NG1 34            // genes/block in K1 (148*34 = 5032 >= 5000)
#define NG1P 36           // padded gene slots
#define GT 40             // genes/block in K3 (125 blocks)

typedef unsigned long long u64;

// Scratch (no allocations allowed)
__device__ __align__(16) float g_partial[NCHUNK][B][K];  // 2.4 MB
__device__ __align__(16) float g_Z[B][K];
__device__ float g_coff[B];

// ---- packed fp32x2 helpers (FFMA2 is PTX-only) ----
__device__ __forceinline__ u64 pack2(float x, float y) {
    u64 r; asm("mov.b64 %0, {%1, %2};" : "=l"(r) : "f"(x), "f"(y)); return r;
}
__device__ __forceinline__ void unpack2(u64 v, float& x, float& y) {
    asm("mov.b64 {%0, %1}, %2;" : "=f"(x), "=f"(y) : "l"(v));
}
__device__ __forceinline__ void ffma2(u64& acc, u64 a, u64 b) {
    asm("fma.rn.f32x2 %0, %1, %2, %0;" : "+l"(acc) : "l"(a), "l"(b));
}
__device__ __forceinline__ u64 lds_b64(unsigned a) {
    u64 r; asm volatile("ld.shared.b64 %0, [%1];" : "=l"(r) : "r"(a)); return r;
}
__device__ __forceinline__ void lds_v2b64(unsigned a, u64& x, u64& y) {
    asm volatile("ld.shared.v2.b64 {%0, %1}, [%2];" : "=l"(x), "=l"(y) : "r"(a));
}
__device__ __forceinline__ void sts_b64(unsigned a, u64 v) {
    asm volatile("st.shared.b64 [%0], %1;" :: "r"(a), "l"(v) : "memory");
}
__device__ __forceinline__ void grid_dep_wait() {
    asm volatile("griddepcontrol.wait;" ::: "memory");
}
__device__ __forceinline__ void grid_dep_launch() {
    asm volatile("griddepcontrol.launch_dependents;" ::: "memory");
}

#define FMAXUPD(ACC, T, MV)                         \
    ACC.x = fmaxf(ACC.x, (T) * MV.x);               \
    ACC.y = fmaxf(ACC.y, (T) * MV.y);               \
    ACC.z = fmaxf(ACC.z, (T) * MV.z);               \
    ACC.w = fmaxf(ACC.w, (T) * MV.w);

// ---------------------------------------------------------------------------
// K1: max-pool. 148 blocks x 1024 threads, 1 CTA/SM.
// M tile staged once to smem; t staged as ts4[gl][h] float4 so the inner
// loop is exactly 2 LDS.128 (immediate offsets) + 32 flop ops per u.
// Thread (q4, h, ge): b-quad h, k-quad q4, genes ge+4u (u=0..8).
// ---------------------------------------------------------------------------
__global__ __launch_bounds__(1024) void k1_maxpool(
    const float* __restrict__ t, const float* __restrict__ M)
{
    extern __shared__ float s1[];
    float*  ts   = s1;                         // ts4[gl][h] float4 = 576 floats
    float*  Ms   = s1 + 576;                   // [NG1P][256] = 9216
    float4* red4 = (float4*)(s1 + 576 + 9216); // [64][64] float4 = 64 KB

    const int tid = threadIdx.x;
    const int g0  = blockIdx.x * NG1;

    // stage t transposed: ts4[gl*16 + h*4 + ii] = t[4h+ii][g0+gl]
    if (tid < NG1P * 16) {
        int gl = tid >> 4;
        int b  = tid & 15;              // b = 4h+ii, layout matches float4 [gl][h]
        int g  = g0 + gl;
        ts[gl * 16 + b] = (gl < NG1 && g < G) ? t[b * G + g] : 0.0f;
    }
    for (int i = tid; i < NG1P * 64; i += 1024) {
        int gl = i >> 6, jq = i & 63;
        int g = g0 + gl;
        float4 v = (gl < NG1 && g < G)
                 ? *(const float4*)(M + (size_t)g * K + 4 * jq)
                 : make_float4(0.f, 0.f, 0.f, 0.f);
        *(float4*)(Ms + gl * 256 + 4 * jq) = v;
    }
    __syncthreads();

    const int q4 = tid & 63;
    const int h  = (tid >> 6) & 3;
    const int ge = tid >> 8;

    const float4* MsV = (const float4*)Ms + ge * 64 + q4;   // +256 f4 per u
    const float4* TsV = (const float4*)ts + ge * 4 + h;     // +16  f4 per u

    float4 acc[4];
#pragma unroll
    for (int ii = 0; ii < 4; ii++) acc[ii] = make_float4(0.f, 0.f, 0.f, 0.f);

#pragma unroll
    for (int u = 0; u < 9; u++) {
        float4 m  = MsV[u * 256];      // immediate offset LDS.128
        float4 tq = TsV[u * 16];       // broadcast LDS.128 (t for 4 b's)
        FMAXUPD(acc[0], tq.x, m)
        FMAXUPD(acc[1], tq.y, m)
        FMAXUPD(acc[2], tq.z, m)
        FMAXUPD(acc[3], tq.w, m)
    }

#pragma unroll
    for (int ii = 0; ii < 4; ii++)
        red4[(((ge * 4 + h) * 4 + ii) << 6) + q4] = acc[ii];
    __syncthreads();

    if (tid < 256) {
        int q4r = tid & 63, hr = tid >> 6;
#pragma unroll
        for (int ii = 0; ii < 4; ii++) {
            float4 a = red4[(((0 * 4 + hr) * 4 + ii) << 6) + q4r];
            float4 c = red4[(((1 * 4 + hr) * 4 + ii) << 6) + q4r];
            float4 d = red4[(((2 * 4 + hr) * 4 + ii) << 6) + q4r];
            float4 e = red4[(((3 * 4 + hr) * 4 + ii) << 6) + q4r];
            float4 r;
            r.x = fmaxf(fmaxf(a.x, c.x), fmaxf(d.x, e.x));
            r.y = fmaxf(fmaxf(a.y, c.y), fmaxf(d.y, e.y));
            r.z = fmaxf(fmaxf(a.z, c.z), fmaxf(d.z, e.z));
            r.w = fmaxf(fmaxf(a.w, c.w), fmaxf(d.w, e.w));
            *(float4*)(&g_partial[blockIdx.x][4 * hr + ii][4 * q4r]) = r;
        }
    }
    __syncthreads();
    grid_dep_launch();     // release K2's wait before CTA drain
}
#define K1_SMEM ((576 + 9216 + 64 * 64 * 4) * (int)sizeof(float))

// ---------------------------------------------------------------------------
// K2: APPNP, packed fp32x2 FMA. 16 blocks x 1024 threads.
// Thread (q, k) owns j in [64q, 64q+64) as 32 pairs: 10 in smem, 22 in regs.
// PDL: stages A + cell offset before griddepcontrol.wait; triggers K3 after
// g_Z store.
// ---------------------------------------------------------------------------
#define K2_ASM_BYTES (40 * 256 * 8)
#define K2_SMEM_BYTES (K2_ASM_BYTES + 1024 + 4096)

__global__ __launch_bounds__(1024, 1) void k2_appnp(
    const float* __restrict__ A,
    const int*   __restrict__ cell_idx,
    const float* __restrict__ cell_emb,
    const float* __restrict__ W2,
    const float* __restrict__ b2)
{
    extern __shared__ float sm[];
    float* Zs   = sm + K2_ASM_BYTES / 4;           // 256 floats
    float* pred = Zs + 256;                         // 1024 floats
    const unsigned abase = (unsigned)__cvta_generic_to_shared(sm);
    const unsigned zbase = abase + K2_ASM_BYTES;

    const int tid = threadIdx.x;
    const int b   = blockIdx.x;
    const int q   = tid >> 8;
    const int k   = tid & 255;

    // --- pre-wait: register A pairs, j in [64q+20, 64q+64) ---
    u64 regA2[22];
#pragma unroll
    for (int u = 0; u < 22; u++) {
        int j0 = 64 * q + 20 + 2 * u;
        regA2[u] = pack2(A[j0 * K + k], A[(j0 + 1) * K + k]);
    }

    // --- pre-wait: smem A pairs: rows r = q*10 + jj, j = 64q + 2jj ---
    for (int i = tid; i < 40 * 256; i += 1024) {
        int r = i >> 8, kk = i & 255;
        int jq = r / 10, jj = r - 10 * jq;
        int j0 = 64 * jq + 2 * jj;
        u64 pk = pack2(A[j0 * K + kk], A[j0 * K + K + kk]);
        sts_b64(abase + (unsigned)(i * 8), pk);
    }

    // --- pre-wait: cell offset ---
    if (tid >= 992) {
        int lane = tid - 992;
        int ci = cell_idx[b];
        float v = cell_emb[ci * HID + lane] * W2[lane]
                + cell_emb[ci * HID + 32 + lane] * W2[32 + lane];
#pragma unroll
        for (int o = 16; o > 0; o >>= 1)
            v += __shfl_down_sync(0xffffffffu, v, o);
        if (lane == 0) g_coff[b] = v + b2[0];
    }

    grid_dep_wait();

    {
        float m = 0.0f;
        const float* gp = &g_partial[q * 37][b][k];
#pragma unroll
        for (int c = 0; c < 37; c++)
            m = fmaxf(m, gp[c * (B * K)]);
        pred[tid] = m;
    }
    __syncthreads();

    const float s_k = fmaxf(fmaxf(pred[k], pred[256 + k]),
                            fmaxf(pred[512 + k], pred[768 + k]));
    if (q == 0) Zs[k] = s_k;
    __syncthreads();

    const unsigned zA = zbase + (unsigned)(64 * q * 4);     // j = 64q..
    const unsigned zB = zA + 20 * 4;                         // j = 64q+20..
    const unsigned aTh = abase + (unsigned)(((q * 10) * 256 + k) * 8);

#pragma unroll 1
    for (int s = 0; s < STEPS; s++) {
        u64 acc = 0;
#pragma unroll
        for (int i = 0; i < 5; i++) {
            u64 z0, z1;
            lds_v2b64(zA + 16 * i, z0, z1);
            u64 a0 = lds_b64(aTh + (unsigned)((2 * i) * 256 * 8));
            u64 a1 = lds_b64(aTh + (unsigned)((2 * i + 1) * 256 * 8));
            ffma2(acc, a0, z0);
            ffma2(acc, a1, z1);
        }
#pragma unroll
        for (int i = 0; i < 11; i++) {
            u64 z0, z1;
            lds_v2b64(zB + 16 * i, z0, z1);
            ffma2(acc, regA2[2 * i], z0);
            ffma2(acc, regA2[2 * i + 1], z1);
        }
        float lo, hi;
        unpack2(acc, lo, hi);
        pred[tid] = lo + hi;
        __syncthreads();
        float v = (pred[k] + pred[256 + k]) + (pred[512 + k] + pred[768 + k]);
        float zn = fmaf(0.9f, v, 0.1f * s_k);
        if (q == 0) Zs[k] = zn;
        __syncthreads();
    }

    if (q == 0) g_Z[b][k] = Zs[k];
    __threadfence();
    __syncthreads();
    grid_dep_launch();     // release K3's wait before CTA drain
}

// ---------------------------------------------------------------------------
// K3: z_gene + MLP + out. 125 blocks x 1024 threads, 40 genes/block.
// Phase B is fully unrolled: 6 disjoint 43-j ranges covering 258 slots;
// Z columns 256,257 are zero and Ms has an 8-float zero pad, so the two
// padded iterations contribute exactly 0.
// ---------------------------------------------------------------------------
#define K3_MS     0        // [40][257] + 8 pad = 10288
#define K3_Z4     10288    // [258][4] float4 = 4128
#define K3_ZPART  14416    // [6][4][40] float4 = 3840
#define K3_WPACK  18256    // 256
#define K3_W2S    18512    // 64
#define K3_CTS    18576    // 640
#define K3_TTS    19216    // 640
#define K3_COFF   19856    // 16
#define K3_ZFIN   19872    // 640
#define K3_YPART  20512    // 1280
#define K3_FLOATS 21792

__global__ __launch_bounds__(1024) void k3_out(
    const float* __restrict__ ctl,
    const float* __restrict__ t,
    const float* __restrict__ M,
    const float* __restrict__ W1,
    const float* __restrict__ b1,
    const float* __restrict__ W2,
    float* __restrict__ out)
{
    extern __shared__ float s3[];
    float*  Ms     = s3 + K3_MS;
    float4* Z4     = (float4*)(s3 + K3_Z4);
    float4* zpart  = (float4*)(s3 + K3_ZPART);
    float4* wpack  = (float4*)(s3 + K3_WPACK);
    float*  W2s    = s3 + K3_W2S;
    float*  cts    = s3 + K3_CTS;
    float*  tts    = s3 + K3_TTS;
    float*  coffs  = s3 + K3_COFF;
    float*  zfin   = s3 + K3_ZFIN;
    float2* ypart  = (float2*)(s3 + K3_YPART);

    const int tid = threadIdx.x;
    const int g0  = blockIdx.x * GT;

    // ---------- pre-wait staging ----------
    for (int i = tid; i < GT * 64; i += 1024) {
        int gl = i >> 6, jq = i & 63;
        int g = g0 + gl;
        float4 v = (g < G) ? *(const float4*)(M + (size_t)g * K + 4 * jq)
                           : make_float4(0.f, 0.f, 0.f, 0.f);
        float* d = Ms + gl * 257 + 4 * jq;
        d[0] = v.x; d[1] = v.y; d[2] = v.z; d[3] = v.w;
    }
    if (tid < 8) Ms[40 * 257 + tid] = 0.0f;               // zero pad after Ms
    if (tid < 8) Z4[256 * 4 + tid] = make_float4(0.f, 0.f, 0.f, 0.f); // j=256,257
    if (tid < 64) {
        wpack[tid] = make_float4(W1[tid], W1[HID + tid], W1[2 * HID + tid], b1[tid]);
        W2s[tid]   = W2[tid];
    }
    if (tid < B * GT) {
        int bb = tid / GT, gl = tid % GT;
        int g = g0 + gl;
        cts[tid] = (g < G) ? ctl[bb * G + g] : 0.0f;
        tts[tid] = (g < G) ? t[bb * G + g] : 0.0f;
    }

    grid_dep_wait();

    {
        int p4 = tid >> 8, j = tid & 255;
        float4 zz;
        zz.x = g_Z[4 * p4 + 0][j];
        zz.y = g_Z[4 * p4 + 1][j];
        zz.z = g_Z[4 * p4 + 2][j];
        zz.w = g_Z[4 * p4 + 3][j];
        Z4[j * 4 + p4] = zz;
    }
    if (tid < B) coffs[tid] = g_coff[tid];
    __syncthreads();

    // ---------- Phase B: partial z-dots, fixed 43 iters, unrolled ----------
    if (tid < 960) {
        const int jh = tid / 160;
        const int r  = tid - jh * 160;
        const int p4 = r / 40;
        const int gl = r - p4 * 40;
        const int j0 = jh * 43;                 // 0,43,86,129,172,215
        const float*  Mrow = Ms + gl * 257 + j0;
        const float4* Zj   = Z4 + j0 * 4 + p4;
        float4 acc = make_float4(0.f, 0.f, 0.f, 0.f);
#pragma unroll
        for (int c = 0; c < 43; c++) {
            float  m = Mrow[c];                 // immediate offsets
            float4 z = Zj[c * 4];
            acc.x = fmaf(m, z.x, acc.x);
            acc.y = fmaf(m, z.y, acc.y);
            acc.z = fmaf(m, z.z, acc.z);
            acc.w = fmaf(m, z.w, acc.w);
        }
        zpart[(jh * 4 + p4) * 40 + gl] = acc;
    }
    __syncthreads();

    // ---------- Phase C: reduce over 6 jh ----------
    if (tid < 160) {
        int p4 = tid / 40, gl = tid - p4 * 40;
        float4 s = make_float4(0.f, 0.f, 0.f, 0.f);
#pragma unroll
        for (int jh = 0; jh < 6; jh++) {
            float4 v = zpart[(jh * 4 + p4) * 40 + gl];
            s.x += v.x; s.y += v.y; s.z += v.z; s.w += v.w;
        }
        zfin[(4 * p4 + 0) * 40 + gl] = s.x;
        zfin[(4 * p4 + 1) * 40 + gl] = s.y;
        zfin[(4 * p4 + 2) * 40 + gl] = s.z;
        zfin[(4 * p4 + 3) * 40 + gl] = s.w;
    }
    __syncthreads();

    // ---------- Phase D: partial MLP (32 HID each) ----------
    if (tid < 640) {
        const int jh2 = tid / 320;
        const int r   = tid - jh2 * 320;
        const int p   = r / 40;
        const int gl  = r - p * 40;
        float z0 = zfin[p * 40 + gl],  z1 = zfin[(p + 8) * 40 + gl];
        float c0 = cts[p * 40 + gl],   c1 = cts[(p + 8) * 40 + gl];
        float t0 = tts[p * 40 + gl],   t1 = tts[(p + 8) * 40 + gl];
        float y0 = 0.f, y1 = 0.f;
#pragma unroll
        for (int jj = 0; jj < 32; jj++) {
            int j = 32 * jh2 + jj;
            float4 w = wpack[j];
            float  w2 = W2s[j];
            float v0 = fmaf(c0, w.x, fmaf(t0, w.y, fmaf(z0, w.z, w.w)));
            float v1 = fmaf(c1, w.x, fmaf(t1, w.y, fmaf(z1, w.z, w.w)));
            y0 = fmaf(fmaxf(v0, 0.f), w2, y0);
            y1 = fmaf(fmaxf(v1, 0.f), w2, y1);
        }
        ypart[jh2 * 320 + r] = make_float2(y0, y1);
    }
    __syncthreads();

    // ---------- Phase E: reduce + store ----------
    if (tid < 320) {
        int p = tid / 40, gl = tid - p * 40;
        int g = g0 + gl;
        if (g < G) {
            float2 a = ypart[tid], bb = ypart[320 + tid];
            out[p * G + g]       = (a.x + bb.x) + coffs[p];
            out[(p + 8) * G + g] = (a.y + bb.y) + coffs[p + 8];
        }
    }
}
#define K3_SMEM (K3_FLOATS * (int)sizeof(float))

// ---------------------------------------------------------------------------
// metadata order: ctl, drug_targets, cell_idx, drug_fp, M, A, W1, b1,
//                 cell_emb, W2, b2   -> output [B, G] float32
// ---------------------------------------------------------------------------
extern "C" void kernel_launch(void* const* d_in, const int* in_sizes, int n_in,
                              void* d_out, int out_size)
{
    const float* ctl      = (const float*)d_in[0];
    const float* tgt      = (const float*)d_in[1];
    const int*   cell_idx = (const int*)  d_in[2];
    // d_in[3] = drug_fp (unused by the model)
    const float* M        = (const float*)d_in[4];
    const float* A        = (const float*)d_in[5];
    const float* W1       = (const float*)d_in[6];
    const float* b1       = (const float*)d_in[7];
    const float* cell_emb = (const float*)d_in[8];
    const float* W2       = (const float*)d_in[9];
    const float* b2       = (const float*)d_in[10];
    float* out = (float*)d_out;

    cudaFuncSetAttribute(k1_maxpool,
                         cudaFuncAttributeMaxDynamicSharedMemorySize, K1_SMEM);
    cudaFuncSetAttribute(k2_appnp,
                         cudaFuncAttributeMaxDynamicSharedMemorySize, K2_SMEM_BYTES);
    cudaFuncSetAttribute(k3_out,
                         cudaFuncAttributeMaxDynamicSharedMemorySize, K3_SMEM);

    k1_maxpool<<<NCHUNK, 1024, K1_SMEM>>>(tgt, M);

    cudaLaunchAttribute pdl[1];
    pdl[0].id = cudaLaunchAttributeProgrammaticStreamSerialization;
    pdl[0].val.programmaticStreamSerializationAllowed = 1;

    {
        cudaLaunchConfig_t cfg = {};
        cfg.gridDim = dim3(B, 1, 1);
        cfg.blockDim = dim3(1024, 1, 1);
        cfg.dynamicSmemBytes = K2_SMEM_BYTES;
        cfg.attrs = pdl;
        cfg.numAttrs = 1;
        cudaLaunchKernelEx(&cfg, k2_appnp, A, cell_idx, cell_emb, W2, b2);
    }
    {
        cudaLaunchConfig_t cfg = {};
        cfg.gridDim = dim3((G + GT - 1) / GT, 1, 1);   // 125
        cfg.blockDim = dim3(1024, 1, 1);
        cfg.dynamicSmemBytes = K3_SMEM;
        cfg.attrs = pdl;
        cfg.numAttrs = 1;
        cudaLaunchKernelEx(&cfg, k3_out, ctl, tgt, M, W1, b1, W2, out);
    }
}

// round 12
// speedup vs baseline: 1.0703x; 1.0703x over previous
#include <cuda_runtime.h>

#define B 16
#define G 5000
#define K 256
#define HID 64
#define STEPS 10
#define NCHUNK 148
#define NG1 34            // genes/block in K1 (148*34 = 5032 >= 5000)
#define NG1P 36           // padded gene slots
#define GT 40             // genes/block in K3 (125 blocks)

typedef unsigned long long u64;

// Scratch (no allocations allowed)
__device__ __align__(16) float g_partial[NCHUNK][B][K];  // 2.4 MB
__device__ __align__(16) float g_Z[B][K];
__device__ float g_coff[B];

// ---- packed fp32x2 helpers (FFMA2 is PTX-only) ----
__device__ __forceinline__ u64 pack2(float x, float y) {
    u64 r; asm("mov.b64 %0, {%1, %2};" : "=l"(r) : "f"(x), "f"(y)); return r;
}
__device__ __forceinline__ void unpack2(u64 v, float& x, float& y) {
    asm("mov.b64 {%0, %1}, %2;" : "=f"(x), "=f"(y) : "l"(v));
}
__device__ __forceinline__ void ffma2(u64& acc, u64 a, u64 b) {
    asm("fma.rn.f32x2 %0, %1, %2, %0;" : "+l"(acc) : "l"(a), "l"(b));
}
__device__ __forceinline__ u64 lds_b64(unsigned a) {
    u64 r; asm volatile("ld.shared.b64 %0, [%1];" : "=l"(r) : "r"(a)); return r;
}
__device__ __forceinline__ void lds_v2b64(unsigned a, u64& x, u64& y) {
    asm volatile("ld.shared.v2.b64 {%0, %1}, [%2];" : "=l"(x), "=l"(y) : "r"(a));
}
__device__ __forceinline__ void sts_b64(unsigned a, u64 v) {
    asm volatile("st.shared.b64 [%0], %1;" :: "r"(a), "l"(v) : "memory");
}
__device__ __forceinline__ void grid_dep_wait() {
    asm volatile("griddepcontrol.wait;" ::: "memory");
}

#define FMAXUPD(ACC, T, MV)                         \
    ACC.x = fmaxf(ACC.x, (T) * MV.x);               \
    ACC.y = fmaxf(ACC.y, (T) * MV.y);               \
    ACC.z = fmaxf(ACC.z, (T) * MV.z);               \
    ACC.w = fmaxf(ACC.w, (T) * MV.w);

// ---------------------------------------------------------------------------
// K1: max-pool. 148 blocks x 1024 threads, 1 CTA/SM.
// M tile staged to smem; t staged as ts4[gl][h] float4. Inner loop software-
// pipelined: prefetch (m, tq) for u+1 while computing u. Epilogue reduce+store
// uses all 1024 threads (1 output quad each).
// ---------------------------------------------------------------------------
__global__ __launch_bounds__(1024) void k1_maxpool(
    const float* __restrict__ t, const float* __restrict__ M)
{
    extern __shared__ float s1[];
    float*  ts   = s1;                         // ts4[gl][h] float4 = 576 floats
    float*  Ms   = s1 + 576;                   // [NG1P][256] = 9216
    float4* red4 = (float4*)(s1 + 576 + 9216); // [64][64] float4 = 64 KB

    const int tid = threadIdx.x;
    const int g0  = blockIdx.x * NG1;

    // stage t transposed: ts4[gl*16 + b] = t[b][g0+gl]
    if (tid < NG1P * 16) {
        int gl = tid >> 4;
        int b  = tid & 15;
        int g  = g0 + gl;
        ts[gl * 16 + b] = (gl < NG1 && g < G) ? t[b * G + g] : 0.0f;
    }
    for (int i = tid; i < NG1P * 64; i += 1024) {
        int gl = i >> 6, jq = i & 63;
        int g = g0 + gl;
        float4 v = (gl < NG1 && g < G)
                 ? *(const float4*)(M + (size_t)g * K + 4 * jq)
                 : make_float4(0.f, 0.f, 0.f, 0.f);
        *(float4*)(Ms + gl * 256 + 4 * jq) = v;
    }
    __syncthreads();

    const int q4 = tid & 63;
    const int h  = (tid >> 6) & 3;
    const int ge = tid >> 8;

    const float4* MsV = (const float4*)Ms + ge * 64 + q4;   // +256 f4 per u
    const float4* TsV = (const float4*)ts + ge * 4 + h;     // +16  f4 per u

    float4 acc[4];
#pragma unroll
    for (int ii = 0; ii < 4; ii++) acc[ii] = make_float4(0.f, 0.f, 0.f, 0.f);

    // software pipeline: load u+1 while computing u
    float4 m  = MsV[0];
    float4 tq = TsV[0];
#pragma unroll
    for (int u = 0; u < 9; u++) {
        float4 mn, tn;
        if (u < 8) {
            mn = MsV[(u + 1) * 256];
            tn = TsV[(u + 1) * 16];
        }
        FMAXUPD(acc[0], tq.x, m)
        FMAXUPD(acc[1], tq.y, m)
        FMAXUPD(acc[2], tq.z, m)
        FMAXUPD(acc[3], tq.w, m)
        if (u < 8) { m = mn; tq = tn; }
    }

#pragma unroll
    for (int ii = 0; ii < 4; ii++)
        red4[(((ge * 4 + h) * 4 + ii) << 6) + q4] = acc[ii];
    __syncthreads();

    // full-width reduce+store: thread -> output (b = tid>>6, q4r = tid&63)
    {
        const int q4r = tid & 63;
        const int b   = tid >> 6;
        const int hr  = b >> 2;
        const int ii  = b & 3;
        float4 a = red4[(((0 * 4 + hr) * 4 + ii) << 6) + q4r];
        float4 c = red4[(((1 * 4 + hr) * 4 + ii) << 6) + q4r];
        float4 d = red4[(((2 * 4 + hr) * 4 + ii) << 6) + q4r];
        float4 e = red4[(((3 * 4 + hr) * 4 + ii) << 6) + q4r];
        float4 r;
        r.x = fmaxf(fmaxf(a.x, c.x), fmaxf(d.x, e.x));
        r.y = fmaxf(fmaxf(a.y, c.y), fmaxf(d.y, e.y));
        r.z = fmaxf(fmaxf(a.z, c.z), fmaxf(d.z, e.z));
        r.w = fmaxf(fmaxf(a.w, c.w), fmaxf(d.w, e.w));
        *(float4*)(&g_partial[blockIdx.x][b][4 * q4r]) = r;
    }
}
#define K1_SMEM ((576 + 9216 + 64 * 64 * 4) * (int)sizeof(float))

// ---------------------------------------------------------------------------
// K2: APPNP, packed fp32x2 FMA. 16 blocks x 1024 threads.
// Thread (q, k) owns j in [64q, 64q+64) as 32 pairs: 10 in smem, 22 in regs.
// PDL: stages A + cell offset before griddepcontrol.wait.
// ---------------------------------------------------------------------------
#define K2_ASM_BYTES (40 * 256 * 8)
#define K2_SMEM_BYTES (K2_ASM_BYTES + 1024 + 4096)

__global__ __launch_bounds__(1024, 1) void k2_appnp(
    const float* __restrict__ A,
    const int*   __restrict__ cell_idx,
    const float* __restrict__ cell_emb,
    const float* __restrict__ W2,
    const float* __restrict__ b2)
{
    extern __shared__ float sm[];
    float* Zs   = sm + K2_ASM_BYTES / 4;           // 256 floats
    float* pred = Zs + 256;                         // 1024 floats
    const unsigned abase = (unsigned)__cvta_generic_to_shared(sm);
    const unsigned zbase = abase + K2_ASM_BYTES;

    const int tid = threadIdx.x;
    const int b   = blockIdx.x;
    const int q   = tid >> 8;
    const int k   = tid & 255;

    // --- pre-wait: register A pairs, j in [64q+20, 64q+64) ---
    u64 regA2[22];
#pragma unroll
    for (int u = 0; u < 22; u++) {
        int j0 = 64 * q + 20 + 2 * u;
        regA2[u] = pack2(A[j0 * K + k], A[(j0 + 1) * K + k]);
    }

    // --- pre-wait: smem A pairs: rows r = q*10 + jj, j = 64q + 2jj ---
    for (int i = tid; i < 40 * 256; i += 1024) {
        int r = i >> 8, kk = i & 255;
        int jq = r / 10, jj = r - 10 * jq;
        int j0 = 64 * jq + 2 * jj;
        u64 pk = pack2(A[j0 * K + kk], A[j0 * K + K + kk]);
        sts_b64(abase + (unsigned)(i * 8), pk);
    }

    // --- pre-wait: cell offset ---
    if (tid >= 992) {
        int lane = tid - 992;
        int ci = cell_idx[b];
        float v = cell_emb[ci * HID + lane] * W2[lane]
                + cell_emb[ci * HID + 32 + lane] * W2[32 + lane];
#pragma unroll
        for (int o = 16; o > 0; o >>= 1)
            v += __shfl_down_sync(0xffffffffu, v, o);
        if (lane == 0) g_coff[b] = v + b2[0];
    }

    grid_dep_wait();

    {
        float m = 0.0f;
        const float* gp = &g_partial[q * 37][b][k];
#pragma unroll
        for (int c = 0; c < 37; c++)
            m = fmaxf(m, gp[c * (B * K)]);
        pred[tid] = m;
    }
    __syncthreads();

    const float s_k = fmaxf(fmaxf(pred[k], pred[256 + k]),
                            fmaxf(pred[512 + k], pred[768 + k]));
    if (q == 0) Zs[k] = s_k;
    __syncthreads();

    const unsigned zA = zbase + (unsigned)(64 * q * 4);     // j = 64q..
    const unsigned zB = zA + 20 * 4;                         // j = 64q+20..
    const unsigned aTh = abase + (unsigned)(((q * 10) * 256 + k) * 8);

#pragma unroll 1
    for (int s = 0; s < STEPS; s++) {
        u64 acc = 0;
#pragma unroll
        for (int i = 0; i < 5; i++) {
            u64 z0, z1;
            lds_v2b64(zA + 16 * i, z0, z1);
            u64 a0 = lds_b64(aTh + (unsigned)((2 * i) * 256 * 8));
            u64 a1 = lds_b64(aTh + (unsigned)((2 * i + 1) * 256 * 8));
            ffma2(acc, a0, z0);
            ffma2(acc, a1, z1);
        }
#pragma unroll
        for (int i = 0; i < 11; i++) {
            u64 z0, z1;
            lds_v2b64(zB + 16 * i, z0, z1);
            ffma2(acc, regA2[2 * i], z0);
            ffma2(acc, regA2[2 * i + 1], z1);
        }
        float lo, hi;
        unpack2(acc, lo, hi);
        pred[tid] = lo + hi;
        __syncthreads();
        float v = (pred[k] + pred[256 + k]) + (pred[512 + k] + pred[768 + k]);
        float zn = fmaf(0.9f, v, 0.1f * s_k);
        if (q == 0) Zs[k] = zn;
        __syncthreads();
    }

    if (q == 0) g_Z[b][k] = Zs[k];
}

// ---------------------------------------------------------------------------
// K3: z_gene + MLP + out. 125 blocks x 1024 threads, 40 genes/block.
// Phase B fully unrolled over fixed 43-j ranges (258 slots, 2 zero-padded).
// ---------------------------------------------------------------------------
#define K3_MS     0        // [40][257] + 8 pad = 10288
#define K3_Z4     10288    // [258][4] float4 = 4128
#define K3_ZPART  14416    // [6][4][40] float4 = 3840
#define K3_WPACK  18256    // 256
#define K3_W2S    18512    // 64
#define K3_CTS    18576    // 640
#define K3_TTS    19216    // 640
#define K3_COFF   19856    // 16
#define K3_ZFIN   19872    // 640
#define K3_YPART  20512    // 1280
#define K3_FLOATS 21792

__global__ __launch_bounds__(1024) void k3_out(
    const float* __restrict__ ctl,
    const float* __restrict__ t,
    const float* __restrict__ M,
    const float* __restrict__ W1,
    const float* __restrict__ b1,
    const float* __restrict__ W2,
    float* __restrict__ out)
{
    extern __shared__ float s3[];
    float*  Ms     = s3 + K3_MS;
    float4* Z4     = (float4*)(s3 + K3_Z4);
    float4* zpart  = (float4*)(s3 + K3_ZPART);
    float4* wpack  = (float4*)(s3 + K3_WPACK);
    float*  W2s    = s3 + K3_W2S;
    float*  cts    = s3 + K3_CTS;
    float*  tts    = s3 + K3_TTS;
    float*  coffs  = s3 + K3_COFF;
    float*  zfin   = s3 + K3_ZFIN;
    float2* ypart  = (float2*)(s3 + K3_YPART);

    const int tid = threadIdx.x;
    const int g0  = blockIdx.x * GT;

    // ---------- pre-wait staging ----------
    for (int i = tid; i < GT * 64; i += 1024) {
        int gl = i >> 6, jq = i & 63;
        int g = g0 + gl;
        float4 v = (g < G) ? *(const float4*)(M + (size_t)g * K + 4 * jq)
                           : make_float4(0.f, 0.f, 0.f, 0.f);
        float* d = Ms + gl * 257 + 4 * jq;
        d[0] = v.x; d[1] = v.y; d[2] = v.z; d[3] = v.w;
    }
    if (tid < 8) Ms[40 * 257 + tid] = 0.0f;
    if (tid < 8) Z4[256 * 4 + tid] = make_float4(0.f, 0.f, 0.f, 0.f);
    if (tid < 64) {
        wpack[tid] = make_float4(W1[tid], W1[HID + tid], W1[2 * HID + tid], b1[tid]);
        W2s[tid]   = W2[tid];
    }
    if (tid < B * GT) {
        int bb = tid / GT, gl = tid % GT;
        int g = g0 + gl;
        cts[tid] = (g < G) ? ctl[bb * G + g] : 0.0f;
        tts[tid] = (g < G) ? t[bb * G + g] : 0.0f;
    }

    grid_dep_wait();

    {
        int p4 = tid >> 8, j = tid & 255;
        float4 zz;
        zz.x = g_Z[4 * p4 + 0][j];
        zz.y = g_Z[4 * p4 + 1][j];
        zz.z = g_Z[4 * p4 + 2][j];
        zz.w = g_Z[4 * p4 + 3][j];
        Z4[j * 4 + p4] = zz;
    }
    if (tid < B) coffs[tid] = g_coff[tid];
    __syncthreads();

    // ---------- Phase B: partial z-dots, fixed 43 iters, unrolled ----------
    if (tid < 960) {
        const int jh = tid / 160;
        const int r  = tid - jh * 160;
        const int p4 = r / 40;
        const int gl = r - p4 * 40;
        const int j0 = jh * 43;
        const float*  Mrow = Ms + gl * 257 + j0;
        const float4* Zj   = Z4 + j0 * 4 + p4;
        float4 acc = make_float4(0.f, 0.f, 0.f, 0.f);
#pragma unroll
        for (int c = 0; c < 43; c++) {
            float  m = Mrow[c];
            float4 z = Zj[c * 4];
            acc.x = fmaf(m, z.x, acc.x);
            acc.y = fmaf(m, z.y, acc.y);
            acc.z = fmaf(m, z.z, acc.z);
            acc.w = fmaf(m, z.w, acc.w);
        }
        zpart[(jh * 4 + p4) * 40 + gl] = acc;
    }
    __syncthreads();

    // ---------- Phase C: reduce over 6 jh ----------
    if (tid < 160) {
        int p4 = tid / 40, gl = tid - p4 * 40;
        float4 s = make_float4(0.f, 0.f, 0.f, 0.f);
#pragma unroll
        for (int jh = 0; jh < 6; jh++) {
            float4 v = zpart[(jh * 4 + p4) * 40 + gl];
            s.x += v.x; s.y += v.y; s.z += v.z; s.w += v.w;
        }
        zfin[(4 * p4 + 0) * 40 + gl] = s.x;
        zfin[(4 * p4 + 1) * 40 + gl] = s.y;
        zfin[(4 * p4 + 2) * 40 + gl] = s.z;
        zfin[(4 * p4 + 3) * 40 + gl] = s.w;
    }
    __syncthreads();

    // ---------- Phase D: partial MLP (32 HID each) ----------
    if (tid < 640) {
        const int jh2 = tid / 320;
        const int r   = tid - jh2 * 320;
        const int p   = r / 40;
        const int gl  = r - p * 40;
        float z0 = zfin[p * 40 + gl],  z1 = zfin[(p + 8) * 40 + gl];
        float c0 = cts[p * 40 + gl],   c1 = cts[(p + 8) * 40 + gl];
        float t0 = tts[p * 40 + gl],   t1 = tts[(p + 8) * 40 + gl];
        float y0 = 0.f, y1 = 0.f;
#pragma unroll
        for (int jj = 0; jj < 32; jj++) {
            int j = 32 * jh2 + jj;
            float4 w = wpack[j];
            float  w2 = W2s[j];
            float v0 = fmaf(c0, w.x, fmaf(t0, w.y, fmaf(z0, w.z, w.w)));
            float v1 = fmaf(c1, w.x, fmaf(t1, w.y, fmaf(z1, w.z, w.w)));
            y0 = fmaf(fmaxf(v0, 0.f), w2, y0);
            y1 = fmaf(fmaxf(v1, 0.f), w2, y1);
        }
        ypart[jh2 * 320 + r] = make_float2(y0, y1);
    }
    __syncthreads();

    // ---------- Phase E: reduce + store ----------
    if (tid < 320) {
        int p = tid / 40, gl = tid - p * 40;
        int g = g0 + gl;
        if (g < G) {
            float2 a = ypart[tid], bb = ypart[320 + tid];
            out[p * G + g]       = (a.x + bb.x) + coffs[p];
            out[(p + 8) * G + g] = (a.y + bb.y) + coffs[p + 8];
        }
    }
}
#define K3_SMEM (K3_FLOATS * (int)sizeof(float))

// ---------------------------------------------------------------------------
// metadata order: ctl, drug_targets, cell_idx, drug_fp, M, A, W1, b1,
//                 cell_emb, W2, b2   -> output [B, G] float32
// ---------------------------------------------------------------------------
extern "C" void kernel_launch(void* const* d_in, const int* in_sizes, int n_in,
                              void* d_out, int out_size)
{
    const float* ctl      = (const float*)d_in[0];
    const float* tgt      = (const float*)d_in[1];
    const int*   cell_idx = (const int*)  d_in[2];
    // d_in[3] = drug_fp (unused by the model)
    const float* M        = (const float*)d_in[4];
    const float* A        = (const float*)d_in[5];
    const float* W1       = (const float*)d_in[6];
    const float* b1       = (const float*)d_in[7];
    const float* cell_emb = (const float*)d_in[8];
    const float* W2       = (const float*)d_in[9];
    const float* b2       = (const float*)d_in[10];
    float* out = (float*)d_out;

    cudaFuncSetAttribute(k1_maxpool,
                         cudaFuncAttributeMaxDynamicSharedMemorySize, K1_SMEM);
    cudaFuncSetAttribute(k2_appnp,
                         cudaFuncAttributeMaxDynamicSharedMemorySize, K2_SMEM_BYTES);
    cudaFuncSetAttribute(k3_out,
                         cudaFuncAttributeMaxDynamicSharedMemorySize, K3_SMEM);

    k1_maxpool<<<NCHUNK, 1024, K1_SMEM>>>(tgt, M);

    cudaLaunchAttribute pdl[1];
    pdl[0].id = cudaLaunchAttributeProgrammaticStreamSerialization;
    pdl[0].val.programmaticStreamSerializationAllowed = 1;

    {
        cudaLaunchConfig_t cfg = {};
        cfg.gridDim = dim3(B, 1, 1);
        cfg.blockDim = dim3(1024, 1, 1);
        cfg.dynamicSmemBytes = K2_SMEM_BYTES;
        cfg.attrs = pdl;
        cfg.numAttrs = 1;
        cudaLaunchKernelEx(&cfg, k2_appnp, A, cell_idx, cell_emb, W2, b2);
    }
    {
        cudaLaunchConfig_t cfg = {};
        cfg.gridDim = dim3((G + GT - 1) / GT, 1, 1);   // 125
        cfg.blockDim = dim3(1024, 1, 1);
        cfg.dynamicSmemBytes = K3_SMEM;
        cfg.attrs = pdl;
        cfg.numAttrs = 1;
        cudaLaunchKernelEx(&cfg, k3_out, ctl, tgt, M, W1, b1, W2, out);
    }
}